// round 4
// baseline (speedup 1.0000x reference)
#include <cuda_runtime.h>
#include <math.h>
#include <float.h>

#define Bv 2
#define Hv 8
#define Sv 2048
#define Dv 64
#define SCALEv 0.125f

#define OUT_ELEMS ((size_t)Bv*Hv*Sv*Dv)
#define SSZ ((size_t)Sv*(size_t)Sv)

// Scratch: pre-mixed (and pre-mix raw) scores [B,H,S,S]; softmax row stats.
__device__ float g_scr[(size_t)Bv*Hv*Sv*Sv];
__device__ float g_m[(size_t)Bv*Hv*Sv];
__device__ float g_s[(size_t)Bv*Hv*Sv];

// ---------------------------------------------------------------------------
// K1: raw dots = q @ k^T * SCALE, lower-triangular 128x128 tiles only.
// grid (256 tiles incl. skipped upper, B*H), 256 thr, dyn smem 2*128*65*4.
// ---------------------------------------------------------------------------
__global__ __launch_bounds__(256, 2) void k_dots(const float* __restrict__ q,
                                                 const float* __restrict__ k) {
    extern __shared__ float sm[];
    float* Qs = sm;              // [128][65]
    float* Ks = sm + 128 * 65;   // [128][65]

    int it = blockIdx.x >> 4;
    int jt = blockIdx.x & 15;
    if (jt > it) return;         // causal tile skip
    int bh = blockIdx.y;

    const float* qb = q + ((size_t)bh * Sv + (size_t)it * 128) * Dv;
    const float* kb = k + ((size_t)bh * Sv + (size_t)jt * 128) * Dv;

    int t = threadIdx.x;
    // Load 128x64 tiles (each thread: 8 float4 per tile)
#pragma unroll
    for (int l = 0; l < 8; l++) {
        int lin = t + l * 256;          // 0..2047
        int row = lin >> 4;
        int c4  = (lin & 15) << 2;
        float4 a = *(const float4*)(qb + (size_t)row * Dv + c4);
        Qs[row * 65 + c4 + 0] = a.x; Qs[row * 65 + c4 + 1] = a.y;
        Qs[row * 65 + c4 + 2] = a.z; Qs[row * 65 + c4 + 3] = a.w;
        float4 b = *(const float4*)(kb + (size_t)row * Dv + c4);
        Ks[row * 65 + c4 + 0] = b.x; Ks[row * 65 + c4 + 1] = b.y;
        Ks[row * 65 + c4 + 2] = b.z; Ks[row * 65 + c4 + 3] = b.w;
    }
    __syncthreads();

    int tx = t & 15, ty = t >> 4;
    float acc[8][8];
#pragma unroll
    for (int r = 0; r < 8; r++)
#pragma unroll
        for (int c = 0; c < 8; c++) acc[r][c] = 0.f;

#pragma unroll 8
    for (int d = 0; d < 64; d++) {
        float a[8], b[8];
#pragma unroll
        for (int r = 0; r < 8; r++) a[r] = Qs[(ty + 16 * r) * 65 + d];
#pragma unroll
        for (int c = 0; c < 8; c++) b[c] = Ks[(tx + 16 * c) * 65 + d];
#pragma unroll
        for (int r = 0; r < 8; r++)
#pragma unroll
            for (int c = 0; c < 8; c++) acc[r][c] = fmaf(a[r], b[c], acc[r][c]);
    }

    size_t obase = (size_t)bh * SSZ;
#pragma unroll
    for (int r = 0; r < 8; r++) {
        int i = it * 128 + ty + 16 * r;
        float* orow = g_scr + obase + (size_t)i * Sv + jt * 128;
#pragma unroll
        for (int c = 0; c < 8; c++) orow[tx + 16 * c] = acc[r][c] * SCALEv;
    }
}

// ---------------------------------------------------------------------------
// K2: in-place pre-softmax head mixing (pre_w) over j<=i, fused with online
// softmax row stats (max, sumexp) per mixed head g. grid (S, B), 256 thr.
// mask is int32 (bool promoted by harness); nonzero == true.
// ---------------------------------------------------------------------------
__global__ __launch_bounds__(256) void k_mix(const float* __restrict__ pre_w,
                                             const int* __restrict__ mask) {
    int i = blockIdx.x;
    int b = blockIdx.y;
    __shared__ float w[64];
    __shared__ float rm[64], rs[64];   // [warp][g]
    int t = threadIdx.x;
    if (t < 64) w[t] = pre_w[t];
    __syncthreads();

    float m[8], s[8];
#pragma unroll
    for (int g = 0; g < 8; g++) { m[g] = -FLT_MAX; s[g] = 0.f; }

    size_t base0 = ((size_t)b * 8 * Sv + i) * Sv;
    const int* mrow = mask + (size_t)b * Sv;

    for (int j = t; j <= i; j += 256) {
        float x[8];
#pragma unroll
        for (int h = 0; h < 8; h++) x[h] = g_scr[base0 + (size_t)h * SSZ + j];
        float y[8];
#pragma unroll
        for (int g = 0; g < 8; g++) {
            float a = x[0] * w[g];
#pragma unroll
            for (int h = 1; h < 8; h++) a = fmaf(x[h], w[h * 8 + g], a);
            y[g] = a;
        }
#pragma unroll
        for (int g = 0; g < 8; g++) g_scr[base0 + (size_t)g * SSZ + j] = y[g];
        if (mrow[j] != 0) {
#pragma unroll
            for (int g = 0; g < 8; g++) {
                float M = fmaxf(m[g], y[g]);
                s[g] = s[g] * __expf(m[g] - M) + __expf(y[g] - M);
                m[g] = M;
            }
        }
    }

    // warp reduce (m,s) pairs
#pragma unroll
    for (int g = 0; g < 8; g++) {
#pragma unroll
        for (int o = 16; o > 0; o >>= 1) {
            float m2 = __shfl_down_sync(0xffffffffu, m[g], o);
            float s2 = __shfl_down_sync(0xffffffffu, s[g], o);
            float M = fmaxf(m[g], m2);
            s[g] = s[g] * __expf(m[g] - M) + s2 * __expf(m2 - M);
            m[g] = M;
        }
    }
    int warp = t >> 5, lane = t & 31;
    if (lane == 0) {
#pragma unroll
        for (int g = 0; g < 8; g++) { rm[warp * 8 + g] = m[g]; rs[warp * 8 + g] = s[g]; }
    }
    __syncthreads();
    if (t < 8) {
        float M = rm[t], Sa = rs[t];
#pragma unroll
        for (int wp = 1; wp < 8; wp++) {
            float m2 = rm[wp * 8 + t], s2 = rs[wp * 8 + t];
            float MM = fmaxf(M, m2);
            Sa = Sa * __expf(M - MM) + s2 * __expf(m2 - MM);
            M = MM;
        }
        g_m[((size_t)b * 8 + t) * Sv + i] = M;
        g_s[((size_t)b * 8 + t) * Sv + i] = Sa;
    }
}

// ---------------------------------------------------------------------------
// K3: normalize + post_w mixing, write full attn output (zeros above diag).
// grid (S/256, S, B), 256 thr.
// ---------------------------------------------------------------------------
__global__ __launch_bounds__(256) void k_post(const float* __restrict__ post_w,
                                              const int* __restrict__ mask,
                                              float* __restrict__ attn) {
    int t = threadIdx.x;
    int j = blockIdx.x * 256 + t;
    int i = blockIdx.y;
    int b = blockIdx.z;
    __shared__ float w[64];
    __shared__ float sm_m[8], sinv[8];
    if (t < 64) w[t] = post_w[t];
    if (t < 8)       sm_m[t]     = g_m[((size_t)b * 8 + t) * Sv + i];
    else if (t < 16) sinv[t - 8] = 1.f / g_s[((size_t)b * 8 + (t - 8)) * Sv + i];
    __syncthreads();

    size_t base = ((size_t)b * 8 * Sv + i) * Sv + j;
    float p[8];
    if (j <= i && mask[(size_t)b * Sv + j] != 0) {
#pragma unroll
        for (int h = 0; h < 8; h++)
            p[h] = __expf(g_scr[base + (size_t)h * SSZ] - sm_m[h]) * sinv[h];
    } else {
#pragma unroll
        for (int h = 0; h < 8; h++) p[h] = 0.f;
    }
#pragma unroll
    for (int g = 0; g < 8; g++) {
        float a = p[0] * w[g];
#pragma unroll
        for (int h = 1; h < 8; h++) a = fmaf(p[h], w[h * 8 + g], a);
        attn[base + (size_t)g * SSZ] = a;
    }
}

// ---------------------------------------------------------------------------
// K4: out = attn @ v per (b,g). 128-row tiles, 64-wide j tiles, causal skip.
// grid (16, 16), 256 thr, 48KB static smem.
// ---------------------------------------------------------------------------
__global__ __launch_bounds__(256) void k_out(const float* __restrict__ attn,
                                             const float* __restrict__ v,
                                             float* __restrict__ out) {
    __shared__ float As[128 * 64];
    __shared__ float Vs[64 * 64];
    int it = blockIdx.x;
    int bh = blockIdx.y;
    int i0 = it * 128;
    const float* ab = attn + ((size_t)bh * Sv + i0) * Sv;
    const float* vb = v + (size_t)bh * Sv * Dv;

    int t = threadIdx.x, tx = t & 15, ty = t >> 4;
    float acc[8][4];
#pragma unroll
    for (int r = 0; r < 8; r++)
#pragma unroll
        for (int c = 0; c < 4; c++) acc[r][c] = 0.f;

    int jtmax = (i0 + 127) >> 6;  // inclusive (attn is 0 above diagonal)
    for (int jt = 0; jt <= jtmax; jt++) {
        __syncthreads();
#pragma unroll
        for (int l = 0; l < 8; l++) {        // attn tile 128x64
            int lin = t + l * 256;
            int row = lin >> 4;
            int c4  = (lin & 15) << 2;
            *(float4*)(As + row * 64 + c4) =
                *(const float4*)(ab + (size_t)row * Sv + jt * 64 + c4);
        }
#pragma unroll
        for (int l = 0; l < 4; l++) {        // v tile 64x64
            int lin = t + l * 256;
            int row = lin >> 4;
            int c4  = (lin & 15) << 2;
            *(float4*)(Vs + row * 64 + c4) =
                *(const float4*)(vb + (size_t)(jt * 64 + row) * Dv + c4);
        }
        __syncthreads();
#pragma unroll 8
        for (int jj = 0; jj < 64; jj++) {
            float a[8], vv[4];
#pragma unroll
            for (int r = 0; r < 8; r++) a[r] = As[(ty + 16 * r) * 64 + jj];
#pragma unroll
            for (int c = 0; c < 4; c++) vv[c] = Vs[jj * 64 + tx + 16 * c];
#pragma unroll
            for (int r = 0; r < 8; r++)
#pragma unroll
                for (int c = 0; c < 4; c++) acc[r][c] = fmaf(a[r], vv[c], acc[r][c]);
        }
    }

    float* ob = out + ((size_t)bh * Sv + i0) * Dv;
#pragma unroll
    for (int r = 0; r < 8; r++)
#pragma unroll
        for (int c = 0; c < 4; c++)
            ob[(ty + 16 * r) * Dv + tx + 16 * c] = acc[r][c];
}

// ---------------------------------------------------------------------------
extern "C" void kernel_launch(void* const* d_in, const int* in_sizes, int n_in,
                              void* d_out, int out_size) {
    const float* q = (const float*)d_in[0];
    const float* k = (const float*)d_in[1];
    const float* v = (const float*)d_in[2];
    const int*   mask = (const int*)d_in[3];
    const float* pre_w  = (const float*)d_in[4];
    const float* post_w = (const float*)d_in[5];

    float* out  = (float*)d_out;
    float* attn = out + OUT_ELEMS;

    int dots_smem = 2 * 128 * 65 * (int)sizeof(float);
    cudaFuncSetAttribute(k_dots, cudaFuncAttributeMaxDynamicSharedMemorySize, dots_smem);

    k_dots<<<dim3(256, Bv * Hv), 256, dots_smem>>>(q, k);
    k_mix <<<dim3(Sv, Bv), 256>>>(pre_w, mask);
    k_post<<<dim3(Sv / 256, Sv, Bv), 256>>>(post_w, mask, attn);
    k_out <<<dim3(Sv / 128, Bv * Hv), 256>>>(attn, v, out);
}

// round 13
// speedup vs baseline: 1.4105x; 1.4105x over previous
#include <cuda_runtime.h>
#include <math.h>
#include <float.h>

#define Bv 2
#define Hv 8
#define Sv 2048
#define Dv 64
#define SCALEv 0.125f

#define OUT_ELEMS ((size_t)Bv*Hv*Sv*Dv)
#define SSZ ((size_t)Sv*(size_t)Sv)

// Scratch: raw q.k^T scores [B,H,S,S] (lower triangle only ever touched).
__device__ float g_scr[(size_t)Bv*Hv*Sv*Sv];

// ---------------------------------------------------------------------------
// K1: raw dots = q @ k^T * SCALE, lower-triangular 128x128 tiles only.
// grid (256 tiles incl. skipped upper, B*H), 256 thr, dyn smem 2*128*65*4.
// ---------------------------------------------------------------------------
__global__ __launch_bounds__(256, 2) void k_dots(const float* __restrict__ q,
                                                 const float* __restrict__ k) {
    extern __shared__ float sm[];
    float* Qs = sm;              // [128][65]
    float* Ks = sm + 128 * 65;   // [128][65]

    int it = blockIdx.x >> 4;
    int jt = blockIdx.x & 15;
    if (jt > it) return;         // causal tile skip
    int bh = blockIdx.y;

    const float* qb = q + ((size_t)bh * Sv + (size_t)it * 128) * Dv;
    const float* kb = k + ((size_t)bh * Sv + (size_t)jt * 128) * Dv;

    int t = threadIdx.x;
#pragma unroll
    for (int l = 0; l < 8; l++) {
        int lin = t + l * 256;          // 0..2047
        int row = lin >> 4;
        int c4  = (lin & 15) << 2;
        float4 a = *(const float4*)(qb + (size_t)row * Dv + c4);
        Qs[row * 65 + c4 + 0] = a.x; Qs[row * 65 + c4 + 1] = a.y;
        Qs[row * 65 + c4 + 2] = a.z; Qs[row * 65 + c4 + 3] = a.w;
        float4 b = *(const float4*)(kb + (size_t)row * Dv + c4);
        Ks[row * 65 + c4 + 0] = b.x; Ks[row * 65 + c4 + 1] = b.y;
        Ks[row * 65 + c4 + 2] = b.z; Ks[row * 65 + c4 + 3] = b.w;
    }
    __syncthreads();

    int tx = t & 15, ty = t >> 4;
    float acc[8][8];
#pragma unroll
    for (int r = 0; r < 8; r++)
#pragma unroll
        for (int c = 0; c < 8; c++) acc[r][c] = 0.f;

#pragma unroll 8
    for (int d = 0; d < 64; d++) {
        float a[8], b[8];
#pragma unroll
        for (int r = 0; r < 8; r++) a[r] = Qs[(ty + 16 * r) * 65 + d];
#pragma unroll
        for (int c = 0; c < 8; c++) b[c] = Ks[(tx + 16 * c) * 65 + d];
#pragma unroll
        for (int r = 0; r < 8; r++)
#pragma unroll
            for (int c = 0; c < 8; c++) acc[r][c] = fmaf(a[r], b[c], acc[r][c]);
    }

    size_t obase = (size_t)bh * SSZ;
#pragma unroll
    for (int r = 0; r < 8; r++) {
        int i = it * 128 + ty + 16 * r;
        float* orow = g_scr + obase + (size_t)i * Sv + jt * 128;
#pragma unroll
        for (int c = 0; c < 8; c++) orow[tx + 16 * c] = acc[r][c] * SCALEv;
    }
}

// ---------------------------------------------------------------------------
// K2 (fused k_mix + k_post): per row (b, i):
//   Phase 1: read raw dots x[8] for j<=i, pre-mix -> y[8] into SMEM (64KB row
//            buffer), accumulate online (max, sumexp) per mixed head g.
//   Reduce stats across the block.
//   Phase 2: for all j<Sv: p = exp(y - m)/s (0 above diag / masked), post-mix,
//            write attn.
// Saves the g_scr write-back + re-read (~268 MB) vs the split version.
// grid (S, B), 256 thr, dyn smem 8*Sv*4 = 64KB -> 3 blocks/SM.
// mask is int32 (bool promoted by harness); nonzero == true.
// ---------------------------------------------------------------------------
__global__ __launch_bounds__(256) void k_mixpost(const float* __restrict__ pre_w,
                                                 const float* __restrict__ post_w,
                                                 const int* __restrict__ mask,
                                                 float* __restrict__ attn) {
    extern __shared__ float ys[];          // [8][Sv]
    __shared__ float wpre[64], wpost[64];
    __shared__ float rm[64], rs[64];       // [warp][g]
    __shared__ float fm[8], fsinv[8];

    int i = blockIdx.x;
    int b = blockIdx.y;
    int t = threadIdx.x;
    if (t < 64)            wpre[t]       = pre_w[t];
    else if (t < 128)      wpost[t - 64] = post_w[t - 64];
    __syncthreads();

    float m[8], s[8];
#pragma unroll
    for (int g = 0; g < 8; g++) { m[g] = -FLT_MAX; s[g] = 0.f; }

    size_t base0 = ((size_t)b * 8 * Sv + i) * Sv;
    const int* mrow = mask + (size_t)b * Sv;

    // ---- Phase 1: mix + online stats, y kept in smem ----
    for (int j = t; j <= i; j += 256) {
        float x[8];
#pragma unroll
        for (int h = 0; h < 8; h++) x[h] = g_scr[base0 + (size_t)h * SSZ + j];
        float y[8];
#pragma unroll
        for (int g = 0; g < 8; g++) {
            float a = x[0] * wpre[g];
#pragma unroll
            for (int h = 1; h < 8; h++) a = fmaf(x[h], wpre[h * 8 + g], a);
            y[g] = a;
        }
#pragma unroll
        for (int g = 0; g < 8; g++) ys[g * Sv + j] = y[g];
        if (mrow[j] != 0) {
#pragma unroll
            for (int g = 0; g < 8; g++) {
                float M = fmaxf(m[g], y[g]);
                s[g] = s[g] * __expf(m[g] - M) + __expf(y[g] - M);
                m[g] = M;
            }
        }
    }

    // ---- block-wide (m, s) reduction ----
#pragma unroll
    for (int g = 0; g < 8; g++) {
#pragma unroll
        for (int o = 16; o > 0; o >>= 1) {
            float m2 = __shfl_down_sync(0xffffffffu, m[g], o);
            float s2 = __shfl_down_sync(0xffffffffu, s[g], o);
            float M = fmaxf(m[g], m2);
            s[g] = s[g] * __expf(m[g] - M) + s2 * __expf(m2 - M);
            m[g] = M;
        }
    }
    int warp = t >> 5, lane = t & 31;
    if (lane == 0) {
#pragma unroll
        for (int g = 0; g < 8; g++) { rm[warp * 8 + g] = m[g]; rs[warp * 8 + g] = s[g]; }
    }
    __syncthreads();
    if (t < 8) {
        float M = rm[t], Sa = rs[t];
#pragma unroll
        for (int wp = 1; wp < 8; wp++) {
            float m2 = rm[wp * 8 + t], s2 = rs[wp * 8 + t];
            float MM = fmaxf(M, m2);
            Sa = Sa * __expf(M - MM) + s2 * __expf(m2 - MM);
            M = MM;
        }
        fm[t] = M;
        fsinv[t] = 1.f / Sa;
    }
    __syncthreads();

    // ---- Phase 2: normalize + post-mix + write full attn row ----
    size_t abase = base0;   // attn has same [b,h,i,j] layout
    for (int j = t; j < Sv; j += 256) {
        float p[8];
        if (j <= i && mrow[j] != 0) {
#pragma unroll
            for (int h = 0; h < 8; h++)
                p[h] = __expf(ys[h * Sv + j] - fm[h]) * fsinv[h];
        } else {
#pragma unroll
            for (int h = 0; h < 8; h++) p[h] = 0.f;
        }
#pragma unroll
        for (int g = 0; g < 8; g++) {
            float a = p[0] * wpost[g];
#pragma unroll
            for (int h = 1; h < 8; h++) a = fmaf(p[h], wpost[h * 8 + g], a);
            attn[abase + (size_t)g * SSZ + j] = a;
        }
    }
}

// ---------------------------------------------------------------------------
// K3: out = attn @ v per (b,g). 64-row i-tiles, balanced pairing (it, 31-it):
// every block executes exactly 33 j-iterations. grid (16, 16), 256 thr.
// smem ~33.4KB -> all 256 blocks co-resident across 148 SMs.
// Thread layout 16x16: thread (tx,ty) owns rows ty+16r (r<4), cols 4tx..4tx+3.
// ---------------------------------------------------------------------------
#define AS_LD 68   // 64 + 4 pad: kills 2-way ty bank conflict on broadcast reads
__global__ __launch_bounds__(256) void k_out(const float* __restrict__ attn,
                                             const float* __restrict__ v,
                                             float* __restrict__ out) {
    __shared__ float As[64 * AS_LD];
    __shared__ float Vs[64 * 64];

    int bh = blockIdx.y;
    const float* vb = v + (size_t)bh * Sv * Dv;
    int t = threadIdx.x, tx = t & 15, ty = t >> 4;

#pragma unroll
    for (int pass = 0; pass < 2; pass++) {
        int it = pass == 0 ? (int)blockIdx.x : 31 - (int)blockIdx.x;
        int i0 = it * 64;
        const float* ab = attn + ((size_t)bh * Sv + i0) * Sv;

        float4 acc[4];
#pragma unroll
        for (int r = 0; r < 4; r++) acc[r] = make_float4(0.f, 0.f, 0.f, 0.f);

        for (int jt = 0; jt <= it; jt++) {      // jtmax = (i0+63)>>6 = it
            __syncthreads();
#pragma unroll
            for (int l = 0; l < 4; l++) {
                int lin = t + l * 256;          // 0..1023
                int row = lin >> 4;
                int c4  = (lin & 15) << 2;
                float4 a = *(const float4*)(ab + (size_t)row * Sv + jt * 64 + c4);
                *(float4*)(As + row * AS_LD + c4) = a;
                float4 b = *(const float4*)(vb + (size_t)(jt * 64 + row) * Dv + c4);
                *(float4*)(Vs + row * 64 + c4) = b;
            }
            __syncthreads();

#pragma unroll 8
            for (int jj = 0; jj < 64; jj++) {
                float4 v4 = *(const float4*)(Vs + jj * 64 + tx * 4);
                float a0 = As[(ty +  0) * AS_LD + jj];
                float a1 = As[(ty + 16) * AS_LD + jj];
                float a2 = As[(ty + 32) * AS_LD + jj];
                float a3 = As[(ty + 48) * AS_LD + jj];
                acc[0].x = fmaf(a0, v4.x, acc[0].x);
                acc[0].y = fmaf(a0, v4.y, acc[0].y);
                acc[0].z = fmaf(a0, v4.z, acc[0].z);
                acc[0].w = fmaf(a0, v4.w, acc[0].w);
                acc[1].x = fmaf(a1, v4.x, acc[1].x);
                acc[1].y = fmaf(a1, v4.y, acc[1].y);
                acc[1].z = fmaf(a1, v4.z, acc[1].z);
                acc[1].w = fmaf(a1, v4.w, acc[1].w);
                acc[2].x = fmaf(a2, v4.x, acc[2].x);
                acc[2].y = fmaf(a2, v4.y, acc[2].y);
                acc[2].z = fmaf(a2, v4.z, acc[2].z);
                acc[2].w = fmaf(a2, v4.w, acc[2].w);
                acc[3].x = fmaf(a3, v4.x, acc[3].x);
                acc[3].y = fmaf(a3, v4.y, acc[3].y);
                acc[3].z = fmaf(a3, v4.z, acc[3].z);
                acc[3].w = fmaf(a3, v4.w, acc[3].w);
            }
        }

        float* ob = out + ((size_t)bh * Sv + i0) * Dv;
#pragma unroll
        for (int r = 0; r < 4; r++)
            *(float4*)(ob + (size_t)(ty + 16 * r) * Dv + tx * 4) = acc[r];
    }
}

// ---------------------------------------------------------------------------
extern "C" void kernel_launch(void* const* d_in, const int* in_sizes, int n_in,
                              void* d_out, int out_size) {
    const float* q = (const float*)d_in[0];
    const float* k = (const float*)d_in[1];
    const float* v = (const float*)d_in[2];
    const int*   mask = (const int*)d_in[3];
    const float* pre_w  = (const float*)d_in[4];
    const float* post_w = (const float*)d_in[5];

    float* out  = (float*)d_out;
    float* attn = out + OUT_ELEMS;

    int dots_smem = 2 * 128 * 65 * (int)sizeof(float);
    cudaFuncSetAttribute(k_dots, cudaFuncAttributeMaxDynamicSharedMemorySize, dots_smem);
    int mix_smem = 8 * Sv * (int)sizeof(float);   // 64 KB row buffer
    cudaFuncSetAttribute(k_mixpost, cudaFuncAttributeMaxDynamicSharedMemorySize, mix_smem);

    k_dots   <<<dim3(256, Bv * Hv), 256, dots_smem>>>(q, k);
    k_mixpost<<<dim3(Sv, Bv), 256, mix_smem>>>(pre_w, post_w, mask, attn);
    k_out    <<<dim3(Sv / 64 / 2, Bv * Hv), 256>>>(attn, v, out);
}